// round 9
// baseline (speedup 1.0000x reference)
#include <cuda_runtime.h>
#include <cuda_bf16.h>
#include <cstdint>

// VolumeRenderer: NeRF alpha-compositing — fully async/coalesced variant.
// Output layout (tuple flattened): color[3N] | depth[N] | acc[N] | weights[192N]
//
// One warp per ray, 6 samples/lane (blocked).
//  - ALL global reads via cp.async 16B chunks (perfectly coalesced, zero regs):
//      group 0 = depth+sigma (needed first, feeds the scan)
//      group 1 = rgb         (needed last, hidden behind exp/scan)
//  - blocked views read back from smem (free transpose)
//  - weights staged blocked->smem->linear for coalesced STG.64
//
// smem/warp: rgb 2304B + depth 768B + sigma 768B = 3840B (weights reuse depth buf)

#define NS   192
#define SPT  6
#define WPB  8
#define EPSV 1e-10f
#define BORDER 1e10f
#define FULLM 0xffffffffu

__device__ __forceinline__ float fsigmoid(float x) {
    return __fdividef(1.0f, 1.0f + __expf(-x));
}

__device__ __forceinline__ void cpa16(unsigned sdst, const char* gsrc) {
    asm volatile("cp.async.cg.shared.global [%0], [%1], 16;"
                 :: "r"(sdst), "l"(gsrc));
}

__global__ void __launch_bounds__(256)
vr_kernel(const float* __restrict__ depth,
          const float* __restrict__ rgb,
          const float* __restrict__ sigma,
          float* __restrict__ out,
          int n_rays)
{
    __shared__ __align__(16) float sRGB[WPB][NS * 3];  // 2304 B/warp
    __shared__ __align__(16) float sD[WPB][NS];        // 768 B/warp (depth, then weights)
    __shared__ __align__(16) float sS[WPB][NS];        // 768 B/warp (sigma)

    const int wi   = threadIdx.x >> 5;
    const int lane = threadIdx.x & 31;
    const int ray  = blockIdx.x * WPB + wi;
    if (ray >= n_rays) return;            // warp-uniform
    const long base = (long)ray * NS;

    // ---- 1. group 0: depth + sigma (48 chunks of 16B each) ----
    {
        const char* gd = reinterpret_cast<const char*>(depth + base);
        const char* gs = reinterpret_cast<const char*>(sigma + base);
        unsigned sd = (unsigned)__cvta_generic_to_shared(&sD[wi][0]);
        unsigned ss = (unsigned)__cvta_generic_to_shared(&sS[wi][0]);
        cpa16(sd + lane * 16, gd + (long)lane * 16);
        cpa16(ss + lane * 16, gs + (long)lane * 16);
        if (lane < 16) {
            cpa16(sd + (32 + lane) * 16, gd + (long)(32 + lane) * 16);
            cpa16(ss + (32 + lane) * 16, gs + (long)(32 + lane) * 16);
        }
        asm volatile("cp.async.commit_group;" ::: "memory");
    }
    // ---- 2. group 1: rgb (144 chunks of 16B) ----
    {
        const char* gr = reinterpret_cast<const char*>(rgb + base * 3);
        unsigned sr = (unsigned)__cvta_generic_to_shared(&sRGB[wi][0]);
        #pragma unroll
        for (int k = 0; k < 4; k++)
            cpa16(sr + (k * 32 + lane) * 16, gr + (long)(k * 32 + lane) * 16);
        if (lane < 16)
            cpa16(sr + (128 + lane) * 16, gr + (long)(128 + lane) * 16);
        asm volatile("cp.async.commit_group;" ::: "memory");
    }

    // ---- 3. wait depth/sigma only; rgb still in flight ----
    asm volatile("cp.async.wait_group 1;" ::: "memory");
    __syncwarp();

    // ---- 4. blocked readback ----
    float d[SPT], sg[SPT];
    {
        const float2* a = reinterpret_cast<const float2*>(&sD[wi][lane * SPT]);
        const float2* b = reinterpret_cast<const float2*>(&sS[wi][lane * SPT]);
        #pragma unroll
        for (int j = 0; j < 3; j++) {
            float2 v = a[j]; d[2*j]  = v.x; d[2*j+1]  = v.y;
            float2 u = b[j]; sg[2*j] = u.x; sg[2*j+1] = u.y;
        }
    }

    const float dnext = __shfl_down_sync(FULLM, d[0], 1);

    // ---- 5. alpha / survival, local product ----
    float e[SPT];
    float p = 1.0f;
    #pragma unroll
    for (int j = 0; j < SPT; j++) {
        float dn = (j < SPT - 1) ? d[j + 1] : dnext;
        float delta = dn - d[j];
        if (lane == 31 && j == SPT - 1) delta = BORDER;
        float s = fmaxf(sg[j], 0.0f);
        float ex = __expf(-s * delta);
        e[j] = ex;
        p *= (ex + EPSV);
    }

    // ---- 6. warp multiplicative scan -> exclusive transmittance ----
    float incl = p;
    #pragma unroll
    for (int off = 1; off < 32; off <<= 1) {
        float v = __shfl_up_sync(FULLM, incl, off);
        if (lane >= off) incl *= v;
    }
    float t = __shfl_up_sync(FULLM, incl, 1);
    if (lane == 0) t = 1.0f;

    // ---- 7. weights + depth/acc; stage weights blocked into sD ----
    float acc = 0.0f, dep = 0.0f;
    {
        float2* wa = reinterpret_cast<float2*>(&sD[wi][lane * SPT]);
        #pragma unroll
        for (int j = 0; j < SPT; j++) {
            float wj = (1.0f - e[j]) * t;
            t *= (e[j] + EPSV);
            e[j] = wj;                       // reuse e[] as w[]
            acc += wj;
            dep = fmaf(wj, d[j], dep);
        }
        #pragma unroll
        for (int j = 0; j < 3; j++) wa[j] = make_float2(e[2*j], e[2*j+1]);
    }

    // ---- 8. wait rgb; also orders the weight STS for linear readback ----
    asm volatile("cp.async.wait_group 0;" ::: "memory");
    __syncwarp();

    // ---- 9. color pass (blocked rgb view, natural channel order) ----
    float c0 = 0.0f, c1 = 0.0f, c2 = 0.0f;
    {
        const float* rv = &sRGB[wi][lane * (SPT * 3)];
        #pragma unroll
        for (int j = 0; j < SPT; j++) {
            float wj = e[j];
            c0 = fmaf(wj, fsigmoid(rv[3*j + 0]), c0);
            c1 = fmaf(wj, fsigmoid(rv[3*j + 1]), c1);
            c2 = fmaf(wj, fsigmoid(rv[3*j + 2]), c2);
        }
    }

    // ---- 10. coalesced weights store (linear smem -> STG.64) ----
    {
        const float2* wsrc = reinterpret_cast<const float2*>(&sD[wi][0]);
        float2* wout = reinterpret_cast<float2*>(out + (long)5 * n_rays + base);
        #pragma unroll
        for (int k = 0; k < 3; k++) wout[k * 32 + lane] = wsrc[k * 32 + lane];
    }

    // ---- 11. warp reduce 5 scalars ----
    #pragma unroll
    for (int off = 16; off; off >>= 1) {
        acc += __shfl_xor_sync(FULLM, acc, off);
        dep += __shfl_xor_sync(FULLM, dep, off);
        c0  += __shfl_xor_sync(FULLM, c0,  off);
        c1  += __shfl_xor_sync(FULLM, c1,  off);
        c2  += __shfl_xor_sync(FULLM, c2,  off);
    }
    if (lane == 0) {
        out[(long)ray * 3 + 0] = c0;
        out[(long)ray * 3 + 1] = c1;
        out[(long)ray * 3 + 2] = c2;
        out[(long)3 * n_rays + ray] = dep;
        out[(long)4 * n_rays + ray] = acc;
    }
}

extern "C" void kernel_launch(void* const* d_in, const int* in_sizes, int n_in,
                              void* d_out, int out_size)
{
    const float* depth = (const float*)d_in[0];
    const float* rgb   = (const float*)d_in[1];
    const float* sigma = (const float*)d_in[2];
    float* out = (float*)d_out;

    const int n_rays = in_sizes[0] / NS;
    const int blocks = (n_rays + WPB - 1) / WPB;
    vr_kernel<<<blocks, 256>>>(depth, rgb, sigma, out, n_rays);
}

// round 10
// speedup vs baseline: 1.0323x; 1.0323x over previous
#include <cuda_runtime.h>
#include <cuda_bf16.h>
#include <cstdint>

// VolumeRenderer: NeRF alpha-compositing — fully async/coalesced variant.
// Output layout (tuple flattened): color[3N] | depth[N] | acc[N] | weights[192N]
//
// One warp per ray, 6 samples/lane (blocked).
//  - ALL global reads via cp.async 16B chunks (perfectly coalesced, zero regs):
//      group 0 = depth+sigma (needed first, feeds the scan)
//      group 1 = rgb         (needed last, hidden behind exp/scan)
//  - blocked views read back from smem (free transpose)
//  - weights staged blocked->smem->linear for coalesced STG.64
//
// smem/warp: rgb 2304B + depth 768B + sigma 768B = 3840B (weights reuse depth buf)

#define NS   192
#define SPT  6
#define WPB  8
#define EPSV 1e-10f
#define BORDER 1e10f
#define FULLM 0xffffffffu

__device__ __forceinline__ float fsigmoid(float x) {
    return __fdividef(1.0f, 1.0f + __expf(-x));
}

__device__ __forceinline__ void cpa16(unsigned sdst, const char* gsrc) {
    asm volatile("cp.async.cg.shared.global [%0], [%1], 16;"
                 :: "r"(sdst), "l"(gsrc));
}

__global__ void __launch_bounds__(256)
vr_kernel(const float* __restrict__ depth,
          const float* __restrict__ rgb,
          const float* __restrict__ sigma,
          float* __restrict__ out,
          int n_rays)
{
    __shared__ __align__(16) float sRGB[WPB][NS * 3];  // 2304 B/warp
    __shared__ __align__(16) float sD[WPB][NS];        // 768 B/warp (depth, then weights)
    __shared__ __align__(16) float sS[WPB][NS];        // 768 B/warp (sigma)

    const int wi   = threadIdx.x >> 5;
    const int lane = threadIdx.x & 31;
    const int ray  = blockIdx.x * WPB + wi;
    if (ray >= n_rays) return;            // warp-uniform
    const long base = (long)ray * NS;

    // ---- 1. group 0: depth + sigma (48 chunks of 16B each) ----
    {
        const char* gd = reinterpret_cast<const char*>(depth + base);
        const char* gs = reinterpret_cast<const char*>(sigma + base);
        unsigned sd = (unsigned)__cvta_generic_to_shared(&sD[wi][0]);
        unsigned ss = (unsigned)__cvta_generic_to_shared(&sS[wi][0]);
        cpa16(sd + lane * 16, gd + (long)lane * 16);
        cpa16(ss + lane * 16, gs + (long)lane * 16);
        if (lane < 16) {
            cpa16(sd + (32 + lane) * 16, gd + (long)(32 + lane) * 16);
            cpa16(ss + (32 + lane) * 16, gs + (long)(32 + lane) * 16);
        }
        asm volatile("cp.async.commit_group;" ::: "memory");
    }
    // ---- 2. group 1: rgb (144 chunks of 16B) ----
    {
        const char* gr = reinterpret_cast<const char*>(rgb + base * 3);
        unsigned sr = (unsigned)__cvta_generic_to_shared(&sRGB[wi][0]);
        #pragma unroll
        for (int k = 0; k < 4; k++)
            cpa16(sr + (k * 32 + lane) * 16, gr + (long)(k * 32 + lane) * 16);
        if (lane < 16)
            cpa16(sr + (128 + lane) * 16, gr + (long)(128 + lane) * 16);
        asm volatile("cp.async.commit_group;" ::: "memory");
    }

    // ---- 3. wait depth/sigma only; rgb still in flight ----
    asm volatile("cp.async.wait_group 1;" ::: "memory");
    __syncwarp();

    // ---- 4. blocked readback ----
    float d[SPT], sg[SPT];
    {
        const float2* a = reinterpret_cast<const float2*>(&sD[wi][lane * SPT]);
        const float2* b = reinterpret_cast<const float2*>(&sS[wi][lane * SPT]);
        #pragma unroll
        for (int j = 0; j < 3; j++) {
            float2 v = a[j]; d[2*j]  = v.x; d[2*j+1]  = v.y;
            float2 u = b[j]; sg[2*j] = u.x; sg[2*j+1] = u.y;
        }
    }

    const float dnext = __shfl_down_sync(FULLM, d[0], 1);

    // ---- 5. alpha / survival, local product ----
    float e[SPT];
    float p = 1.0f;
    #pragma unroll
    for (int j = 0; j < SPT; j++) {
        float dn = (j < SPT - 1) ? d[j + 1] : dnext;
        float delta = dn - d[j];
        if (lane == 31 && j == SPT - 1) delta = BORDER;
        float s = fmaxf(sg[j], 0.0f);
        float ex = __expf(-s * delta);
        e[j] = ex;
        p *= (ex + EPSV);
    }

    // ---- 6. warp multiplicative scan -> exclusive transmittance ----
    float incl = p;
    #pragma unroll
    for (int off = 1; off < 32; off <<= 1) {
        float v = __shfl_up_sync(FULLM, incl, off);
        if (lane >= off) incl *= v;
    }
    float t = __shfl_up_sync(FULLM, incl, 1);
    if (lane == 0) t = 1.0f;

    // ---- 7. weights + depth/acc; stage weights blocked into sD ----
    float acc = 0.0f, dep = 0.0f;
    {
        float2* wa = reinterpret_cast<float2*>(&sD[wi][lane * SPT]);
        #pragma unroll
        for (int j = 0; j < SPT; j++) {
            float wj = (1.0f - e[j]) * t;
            t *= (e[j] + EPSV);
            e[j] = wj;                       // reuse e[] as w[]
            acc += wj;
            dep = fmaf(wj, d[j], dep);
        }
        #pragma unroll
        for (int j = 0; j < 3; j++) wa[j] = make_float2(e[2*j], e[2*j+1]);
    }

    // ---- 8. wait rgb; also orders the weight STS for linear readback ----
    asm volatile("cp.async.wait_group 0;" ::: "memory");
    __syncwarp();

    // ---- 9. color pass (blocked rgb view, natural channel order) ----
    float c0 = 0.0f, c1 = 0.0f, c2 = 0.0f;
    {
        const float* rv = &sRGB[wi][lane * (SPT * 3)];
        #pragma unroll
        for (int j = 0; j < SPT; j++) {
            float wj = e[j];
            c0 = fmaf(wj, fsigmoid(rv[3*j + 0]), c0);
            c1 = fmaf(wj, fsigmoid(rv[3*j + 1]), c1);
            c2 = fmaf(wj, fsigmoid(rv[3*j + 2]), c2);
        }
    }

    // ---- 10. coalesced weights store (linear smem -> STG.64) ----
    {
        const float2* wsrc = reinterpret_cast<const float2*>(&sD[wi][0]);
        float2* wout = reinterpret_cast<float2*>(out + (long)5 * n_rays + base);
        #pragma unroll
        for (int k = 0; k < 3; k++) wout[k * 32 + lane] = wsrc[k * 32 + lane];
    }

    // ---- 11. warp reduce 5 scalars ----
    #pragma unroll
    for (int off = 16; off; off >>= 1) {
        acc += __shfl_xor_sync(FULLM, acc, off);
        dep += __shfl_xor_sync(FULLM, dep, off);
        c0  += __shfl_xor_sync(FULLM, c0,  off);
        c1  += __shfl_xor_sync(FULLM, c1,  off);
        c2  += __shfl_xor_sync(FULLM, c2,  off);
    }
    if (lane == 0) {
        out[(long)ray * 3 + 0] = c0;
        out[(long)ray * 3 + 1] = c1;
        out[(long)ray * 3 + 2] = c2;
        out[(long)3 * n_rays + ray] = dep;
        out[(long)4 * n_rays + ray] = acc;
    }
}

extern "C" void kernel_launch(void* const* d_in, const int* in_sizes, int n_in,
                              void* d_out, int out_size)
{
    const float* depth = (const float*)d_in[0];
    const float* rgb   = (const float*)d_in[1];
    const float* sigma = (const float*)d_in[2];
    float* out = (float*)d_out;

    const int n_rays = in_sizes[0] / NS;
    const int blocks = (n_rays + WPB - 1) / WPB;
    vr_kernel<<<blocks, 256>>>(depth, rgb, sigma, out, n_rays);
}